// round 1
// baseline (speedup 1.0000x reference)
#include <cuda_runtime.h>
#include <cstdint>

// Problem constants (fixed by the dataset)
#define DMODEL 512
#define NEXP   8
#define KSLOT  2
#define MAXROWS 32768   // worst case: all N*K rows to one expert

// Tiling
#define BM 128
#define BN 128
#define BK 16

// ---------------- scratch (static device allocations are allowed) ----------
__device__ int   g_count[NEXP];
__device__ int   g_token[NEXP * MAXROWS];
__device__ float g_prob [NEXP * MAXROWS];

// ---------------- helpers ---------------------------------------------------
__device__ __forceinline__ unsigned long long fma2(unsigned long long a,
                                                   unsigned long long b,
                                                   unsigned long long c) {
    unsigned long long d;
    asm("fma.rn.f32x2 %0, %1, %2, %3;" : "=l"(d) : "l"(a), "l"(b), "l"(c));
    return d;
}
__device__ __forceinline__ unsigned long long bcast2(float a) {
    unsigned long long r;
    unsigned int ai = __float_as_uint(a);
    asm("mov.b64 %0, {%1, %1};" : "=l"(r) : "r"(ai));
    return r;
}
__device__ __forceinline__ float2 unpack2(unsigned long long v) {
    unsigned int lo, hi;
    asm("mov.b64 {%0, %1}, %2;" : "=r"(lo), "=r"(hi) : "l"(v));
    return make_float2(__uint_as_float(lo), __uint_as_float(hi));
}

// ---------------- kernels ---------------------------------------------------
__global__ void zero_counts_kernel() {
    if (threadIdx.x < NEXP) g_count[threadIdx.x] = 0;
}

__global__ void route_kernel(const int* __restrict__ idx,
                             const float* __restrict__ prob, int total) {
    int i = blockIdx.x * blockDim.x + threadIdx.x;
    if (i < total) {
        int e = idx[i];
        int pos = atomicAdd(&g_count[e], 1);
        g_token[e * MAXROWS + pos] = i / KSLOT;  // token id
        g_prob [e * MAXROWS + pos] = prob[i];
    }
}

// Grouped SGEMM with gathered A rows; fp32x2 packed FMAs; atomicAdd epilogue.
__global__ __launch_bounds__(256, 2)
void moe_gemm_kernel(const float* __restrict__ x,
                     const float* __restrict__ W,
                     const float* __restrict__ bias,
                     float* __restrict__ out) {
    const int e   = blockIdx.z;
    const int cnt = g_count[e];
    const int m0  = blockIdx.y * BM;
    if (m0 >= cnt) return;
    const int n0  = blockIdx.x * BN;

    __shared__ float As[2][BK][BM];
    __shared__ float Bs[2][BK][BN];
    __shared__ int   sTok[BM];
    __shared__ float sPrb[BM];

    const int tid = threadIdx.x;

    // row metadata for this M tile
    if (tid < BM) {
        int r = m0 + tid;
        if (r < cnt) {
            sTok[tid] = g_token[e * MAXROWS + r];
            sPrb[tid] = g_prob [e * MAXROWS + r];
        } else {
            sTok[tid] = 0;
            sPrb[tid] = 0.0f;
        }
    }
    __syncthreads();

    const int tx = tid & 15;   // 0..15 -> output cols tx*8..tx*8+7
    const int ty = tid >> 4;   // 0..15 -> output rows ty*8..ty*8+7

    // global->smem load mapping (2 float4 per thread per tile for A and B)
    int rA[2], cA[2], kB[2], cB[2];
#pragma unroll
    for (int s = 0; s < 2; s++) {
        int lin = tid + 256 * s;
        rA[s] = lin >> 2;  cA[s] = lin & 3;    // A: 128 rows x 4 float4
        kB[s] = lin >> 5;  cB[s] = lin & 31;   // B: 16 rows x 32 float4
    }

    const float* Wbase = W + (size_t)e * DMODEL * DMODEL;

    // preload tile 0
    float4 pa[2], pb[2];
#pragma unroll
    for (int s = 0; s < 2; s++) {
        pa[s] = *(const float4*)(x + (size_t)sTok[rA[s]] * DMODEL + cA[s] * 4);
        pb[s] = *(const float4*)(Wbase + (size_t)kB[s] * DMODEL + n0 + cB[s] * 4);
    }
#pragma unroll
    for (int s = 0; s < 2; s++) {
        As[0][cA[s] * 4 + 0][rA[s]] = pa[s].x;
        As[0][cA[s] * 4 + 1][rA[s]] = pa[s].y;
        As[0][cA[s] * 4 + 2][rA[s]] = pa[s].z;
        As[0][cA[s] * 4 + 3][rA[s]] = pa[s].w;
        *(float4*)&Bs[0][kB[s]][cB[s] * 4] = pb[s];
    }
    __syncthreads();

    unsigned long long acc[8][4];
#pragma unroll
    for (int i = 0; i < 8; i++)
#pragma unroll
        for (int j = 0; j < 4; j++) acc[i][j] = 0ull;

    const int NT = DMODEL / BK;  // 32
    for (int kt = 0; kt < NT; kt++) {
        const int cur = kt & 1;
        const int nxt = cur ^ 1;
        const bool more = (kt + 1 < NT);
        if (more) {
            const int k0n = (kt + 1) * BK;
#pragma unroll
            for (int s = 0; s < 2; s++) {
                pa[s] = *(const float4*)(x + (size_t)sTok[rA[s]] * DMODEL + k0n + cA[s] * 4);
                pb[s] = *(const float4*)(Wbase + (size_t)(k0n + kB[s]) * DMODEL + n0 + cB[s] * 4);
            }
        }

#pragma unroll
        for (int kk = 0; kk < BK; kk++) {
            float4 a0 = *(const float4*)&As[cur][kk][ty * 8];
            float4 a1 = *(const float4*)&As[cur][kk][ty * 8 + 4];
            ulonglong2 b0 = *(const ulonglong2*)&Bs[cur][kk][tx * 8];
            ulonglong2 b1 = *(const ulonglong2*)&Bs[cur][kk][tx * 8 + 4];
            unsigned long long rb[4] = {b0.x, b0.y, b1.x, b1.y};
            float ra[8] = {a0.x, a0.y, a0.z, a0.w, a1.x, a1.y, a1.z, a1.w};
#pragma unroll
            for (int i = 0; i < 8; i++) {
                unsigned long long ap = bcast2(ra[i]);
#pragma unroll
                for (int j = 0; j < 4; j++) acc[i][j] = fma2(ap, rb[j], acc[i][j]);
            }
        }

        if (more) {
#pragma unroll
            for (int s = 0; s < 2; s++) {
                As[nxt][cA[s] * 4 + 0][rA[s]] = pa[s].x;
                As[nxt][cA[s] * 4 + 1][rA[s]] = pa[s].y;
                As[nxt][cA[s] * 4 + 2][rA[s]] = pa[s].z;
                As[nxt][cA[s] * 4 + 3][rA[s]] = pa[s].w;
                *(float4*)&Bs[nxt][kB[s]][cB[s] * 4] = pb[s];
            }
            __syncthreads();
        }
    }

    // epilogue: out[tok, n0+tx*8+j] += p * (acc + bias)
    float bj[8];
#pragma unroll
    for (int j = 0; j < 8; j++)
        bj[j] = bias[e * DMODEL + n0 + tx * 8 + j];

#pragma unroll
    for (int i = 0; i < 8; i++) {
        int rr = ty * 8 + i;
        if (m0 + rr < cnt) {
            int t   = sTok[rr];
            float p = sPrb[rr];
            float* orow = out + (size_t)t * DMODEL + n0 + tx * 8;
#pragma unroll
            for (int j2 = 0; j2 < 4; j2++) {
                float2 v = unpack2(acc[i][j2]);
                atomicAdd(&orow[2 * j2 + 0], p * (v.x + bj[2 * j2 + 0]));
                atomicAdd(&orow[2 * j2 + 1], p * (v.y + bj[2 * j2 + 1]));
            }
        }
    }
}

// ---------------- launch -----------------------------------------------------
extern "C" void kernel_launch(void* const* d_in, const int* in_sizes, int n_in,
                              void* d_out, int out_size) {
    const float* x    = (const float*)d_in[0];
    const float* prob = (const float*)d_in[1];
    const int*   idx  = (const int*)d_in[2];
    const float* W    = (const float*)d_in[3];
    const float* bias = (const float*)d_in[4];
    float* out = (float*)d_out;

    const int NK = in_sizes[2];  // N * K token-slot rows

    // zero the whole output (also zeroes the scalar loss element, if present)
    cudaMemsetAsync(d_out, 0, (size_t)out_size * sizeof(float), 0);

    zero_counts_kernel<<<1, 32>>>();
    route_kernel<<<(NK + 255) / 256, 256>>>(idx, prob, NK);

    dim3 grid(DMODEL / BN, (MAXROWS + BM - 1) / BM, NEXP);
    moe_gemm_kernel<<<grid, 256>>>(x, W, bias, out);
}

// round 3
// speedup vs baseline: 1.3665x; 1.3665x over previous
#include <cuda_runtime.h>
#include <cuda_bf16.h>
#include <cstdint>

// ---------------- problem constants ----------------------------------------
#define DMODEL 512
#define NEXP   8
#define NTOK   16384
#define NKROWS 32768          // NTOK * top_k
#define BM     128
#define BN     128
#define BK     32             // bf16 k per chunk
#define KCAT   1536           // [xh | xh | xl] x [Wh | Wl | Wh]
#define NCH    (KCAT / BK)    // 48
#define ASTR   40             // smem row stride in bf16 elems (32 + 8 pad = 80B)

// ---------------- static device scratch -------------------------------------
__device__ int g_cnt[NEXP], g_cur[NEXP], g_off[NEXP + 1];
__device__ int g_tok[NKROWS];                       // compact row -> token
__device__ int g_row[NKROWS];                       // (token,slot) -> compact row
__device__ __nv_bfloat16 g_xh[NTOK * DMODEL];       // x hi
__device__ __nv_bfloat16 g_xl[NTOK * DMODEL];       // x lo (residual)
__device__ __nv_bfloat16 g_B[NEXP * DMODEL * KCAT]; // [e][n][kcat] = [Wh|Wl|Wh]
__device__ float g_y[(size_t)NKROWS * DMODEL];      // raw expert outputs

// ---------------- helpers ----------------------------------------------------
__device__ __forceinline__ uint32_t smem_u32(const void* p) {
    uint32_t a;
    asm("{ .reg .u64 t; cvta.to.shared.u64 t, %1; cvt.u32.u64 %0, t; }"
        : "=r"(a) : "l"(p));
    return a;
}
__device__ __forceinline__ uint32_t cvt_bf16x2(float hi, float lo) {
    uint32_t r;
    asm("cvt.rn.bf16x2.f32 %0, %1, %2;" : "=r"(r) : "f"(hi), "f"(lo));
    return r;
}
// residual of the two floats packed in h (lo in low half, hi in high half)
__device__ __forceinline__ uint32_t residual_bf16x2(float hi, float lo, uint32_t h) {
    float rh = hi - __uint_as_float(h & 0xffff0000u);
    float rl = lo - __uint_as_float(h << 16);
    return cvt_bf16x2(rh, rl);
}
__device__ __forceinline__ void ldsm_x4(uint32_t* r, uint32_t addr) {
    asm volatile("ldmatrix.sync.aligned.m8n8.x4.shared.b16 {%0,%1,%2,%3}, [%4];"
                 : "=r"(r[0]), "=r"(r[1]), "=r"(r[2]), "=r"(r[3]) : "r"(addr));
}
__device__ __forceinline__ void mma16816(float* c, const uint32_t* a,
                                         uint32_t b0, uint32_t b1) {
    asm volatile(
        "mma.sync.aligned.m16n8k16.row.col.f32.bf16.bf16.f32 "
        "{%0,%1,%2,%3}, {%4,%5,%6,%7}, {%8,%9}, {%0,%1,%2,%3};"
        : "+f"(c[0]), "+f"(c[1]), "+f"(c[2]), "+f"(c[3])
        : "r"(a[0]), "r"(a[1]), "r"(a[2]), "r"(a[3]), "r"(b0), "r"(b1));
}

// ---------------- routing ----------------------------------------------------
__global__ void zero_route_kernel() {
    if (threadIdx.x < NEXP) { g_cnt[threadIdx.x] = 0; g_cur[threadIdx.x] = 0; }
}
__global__ void count_kernel(const int* __restrict__ idx) {
    int i = blockIdx.x * blockDim.x + threadIdx.x;
    if (i < NKROWS) atomicAdd(&g_cnt[idx[i]], 1);
}
__global__ void scan_kernel() {
    if (threadIdx.x == 0) {
        int acc = 0;
        for (int e = 0; e < NEXP; e++) { g_off[e] = acc; acc += g_cnt[e]; }
        g_off[NEXP] = acc;
    }
}
__global__ void place_kernel(const int* __restrict__ idx) {
    int i = blockIdx.x * blockDim.x + threadIdx.x;
    if (i < NKROWS) {
        int e = idx[i];
        int pos = g_off[e] + atomicAdd(&g_cur[e], 1);
        g_tok[pos] = i >> 1;
        g_row[i] = pos;
    }
}

// ---------------- x split (fp32 -> bf16 hi/lo) -------------------------------
__global__ void convert_x_kernel(const float* __restrict__ x) {
    int i = blockIdx.x * blockDim.x + threadIdx.x;   // per 4 floats
    if (i >= NTOK * DMODEL / 4) return;
    float4 v = ((const float4*)x)[i];
    uint32_t h0 = cvt_bf16x2(v.y, v.x);
    uint32_t h1 = cvt_bf16x2(v.w, v.z);
    uint32_t l0 = residual_bf16x2(v.y, v.x, h0);
    uint32_t l1 = residual_bf16x2(v.w, v.z, h1);
    ((uint2*)g_xh)[i] = make_uint2(h0, h1);
    ((uint2*)g_xl)[i] = make_uint2(l0, l1);
}

// ---------------- W transpose + split -> g_B = [Wh | Wl | Wh] ----------------
__global__ void convert_w_kernel(const float* __restrict__ W) {
    __shared__ float tile[32][33];
    int e = blockIdx.z, k0 = blockIdx.x * 32, n0 = blockIdx.y * 32;
    int tx = threadIdx.x, ty = threadIdx.y;
    const float* Wb = W + (size_t)e * DMODEL * DMODEL;
    for (int r = ty; r < 32; r += 8)
        tile[r][tx] = Wb[(size_t)(k0 + r) * DMODEL + n0 + tx];
    __syncthreads();
    __nv_bfloat16* Be = g_B + (size_t)e * DMODEL * KCAT;
    for (int r = ty; r < 32; r += 8) {
        float v = tile[tx][r];                       // = W[k0+tx][n0+r]
        float hf = __bfloat162float(__float2bfloat16_rn(v));
        __nv_bfloat16 h = __float2bfloat16_rn(v);
        __nv_bfloat16 l = __float2bfloat16_rn(v - hf);
        size_t o = (size_t)(n0 + r) * KCAT + k0 + tx;
        Be[o]        = h;
        Be[o + 512]  = l;
        Be[o + 1024] = h;
    }
}

// ---------------- grouped GEMM via mma.sync (HMMA bf16) ----------------------
__global__ __launch_bounds__(256, 1)
void moe_gemm_kernel() {
    const int e = blockIdx.z;
    const int r0 = g_off[e], r1 = g_off[e + 1];
    const int m0 = r0 + blockIdx.y * BM;
    if (m0 >= r1) return;
    const int n0 = blockIdx.x * BN;

    __shared__ __nv_bfloat16 sA[2][BM * ASTR];
    __shared__ __nv_bfloat16 sB[2][BN * ASTR];
    __shared__ int sTok[BM];

    const int tid  = threadIdx.x;
    const int wid  = tid >> 5;
    const int lane = tid & 31;
    const int wm   = wid & 3;    // 4 M slices of 32 rows
    const int wn   = wid >> 2;   // 2 N slices of 64 cols

    if (tid < BM) {
        int r = m0 + tid;
        sTok[tid] = (r < r1) ? g_tok[r] : g_tok[m0];
    }
    __syncthreads();

    // global-load mapping: lr = row (0..127), lh = k-half (0/1, 16 bf16 each)
    const int lr = tid >> 1, lh = tid & 1;
    const size_t xoff = (size_t)sTok[lr] * DMODEL + lh * 16;
    const __nv_bfloat16* Brow =
        g_B + ((size_t)e * DMODEL + n0 + lr) * KCAT + lh * 16;

    uint4 pa0, pa1, pb0, pb1;
    auto loadg = [&](int t) {
        int kc = t * BK;
        int sec = kc >> 9;
        int ksub = kc & 511;
        const __nv_bfloat16* xs = (sec < 2 ? g_xh : g_xl) + xoff + ksub;
        pa0 = *(const uint4*)xs;
        pa1 = *(const uint4*)(xs + 8);
        pb0 = *(const uint4*)(Brow + kc);
        pb1 = *(const uint4*)(Brow + kc + 8);
    };
    auto stores = [&](int st) {
        __nv_bfloat16* da = &sA[st][lr * ASTR + lh * 16];
        __nv_bfloat16* db = &sB[st][lr * ASTR + lh * 16];
        *(uint4*)da = pa0; *(uint4*)(da + 8) = pa1;
        *(uint4*)db = pb0; *(uint4*)(db + 8) = pb1;
    };

    float acc[2][8][4];
#pragma unroll
    for (int i = 0; i < 2; i++)
#pragma unroll
        for (int j = 0; j < 8; j++)
#pragma unroll
            for (int q = 0; q < 4; q++) acc[i][j][q] = 0.0f;

    // ldmatrix lane addressing (byte offsets within a stage)
    // A: matrices (rows0-7,k0)(rows8-15,k0)(rows0-7,k8)(rows8-15,k8)
    const int aRow = wm * 32 + (lane & 7) + ((lane >> 3) & 1) * 8;
    const int aK   = ((lane >> 4) & 1) * 8;
    // B: matrices (n0-7,k0)(n0-7,k8)(n8-15,k0)(n8-15,k8)
    const int bRow = wn * 64 + (lane & 7) + ((lane >> 4) & 1) * 8;
    const int bK   = ((lane >> 3) & 1) * 8;

    const uint32_t sA0 = smem_u32(&sA[0][0]);
    const uint32_t sB0 = smem_u32(&sB[0][0]);
    const uint32_t stageA = (uint32_t)(BM * ASTR * 2); // bytes per stage
    const uint32_t stageB = (uint32_t)(BN * ASTR * 2);

    loadg(0);
    stores(0);
    __syncthreads();

    for (int t = 0; t < NCH; t++) {
        const int st = t & 1;
        const bool more = (t + 1 < NCH);
        if (more) loadg(t + 1);

        const uint32_t aBase = sA0 + st * stageA + (aRow * 80 + aK * 2);
        const uint32_t bBase = sB0 + st * stageB + (bRow * 80 + bK * 2);
#pragma unroll
        for (int k16 = 0; k16 < 2; k16++) {
            uint32_t a[2][4];
#pragma unroll
            for (int mt = 0; mt < 2; mt++)
                ldsm_x4(a[mt], aBase + mt * 16 * 80 + k16 * 32);
            uint32_t b[4][4];
#pragma unroll
            for (int nt2 = 0; nt2 < 4; nt2++)
                ldsm_x4(b[nt2], bBase + nt2 * 16 * 80 + k16 * 32);
#pragma unroll
            for (int mt = 0; mt < 2; mt++)
#pragma unroll
                for (int nt2 = 0; nt2 < 4; nt2++) {
                    mma16816(acc[mt][2 * nt2 + 0], a[mt], b[nt2][0], b[nt2][1]);
                    mma16816(acc[mt][2 * nt2 + 1], a[mt], b[nt2][2], b[nt2][3]);
                }
        }

        if (more) {
            stores(st ^ 1);
            __syncthreads();
        }
    }

    // ---- epilogue: fragments -> g_y (plain stores) ----
    const int qrow = lane >> 2;          // 0..7
    const int qcol = 2 * (lane & 3);     // 0,2,4,6
#pragma unroll
    for (int mt = 0; mt < 2; mt++) {
        int rbase = m0 + wm * 32 + mt * 16 + qrow;
#pragma unroll
        for (int half = 0; half < 2; half++) {
            int grow = rbase + half * 8;
            if (grow < r1) {
                float* yr = g_y + (size_t)grow * DMODEL + n0 + wn * 64 + qcol;
#pragma unroll
                for (int nt = 0; nt < 8; nt++) {
                    float2 v = make_float2(acc[mt][nt][2 * half],
                                           acc[mt][nt][2 * half + 1]);
                    *(float2*)(yr + nt * 8) = v;
                }
            }
        }
    }
}

// ---------------- combine: out[n] = sum_k p * (y[row] + b[e]) ----------------
__global__ void combine_kernel(const float* __restrict__ prob,
                               const int* __restrict__ idx,
                               const float* __restrict__ bias,
                               float* __restrict__ out) {
    int i = blockIdx.x * blockDim.x + threadIdx.x;   // over NTOK * 128
    if (i >= NTOK * (DMODEL / 4)) return;
    int n = i >> 7;
    int c4 = i & 127;
    int e0 = idx[2 * n], e1 = idx[2 * n + 1];
    float p0 = prob[2 * n], p1 = prob[2 * n + 1];
    int rr0 = g_row[2 * n], rr1 = g_row[2 * n + 1];
    float4 y0 = ((const float4*)g_y)[(size_t)rr0 * 128 + c4];
    float4 y1 = ((const float4*)g_y)[(size_t)rr1 * 128 + c4];
    float4 b0 = ((const float4*)(bias + (size_t)e0 * DMODEL))[c4];
    float4 b1 = ((const float4*)(bias + (size_t)e1 * DMODEL))[c4];
    float4 o;
    o.x = p0 * (y0.x + b0.x) + p1 * (y1.x + b1.x);
    o.y = p0 * (y0.y + b0.y) + p1 * (y1.y + b1.y);
    o.z = p0 * (y0.z + b0.z) + p1 * (y1.z + b1.z);
    o.w = p0 * (y0.w + b0.w) + p1 * (y1.w + b1.w);
    ((float4*)out)[(size_t)n * 128 + c4] = o;
}

// ---------------- launch -----------------------------------------------------
extern "C" void kernel_launch(void* const* d_in, const int* in_sizes, int n_in,
                              void* d_out, int out_size) {
    const float* x    = (const float*)d_in[0];
    const float* prob = (const float*)d_in[1];
    const int*   idx  = (const int*)d_in[2];
    const float* W    = (const float*)d_in[3];
    const float* bias = (const float*)d_in[4];
    float* out = (float*)d_out;

    // zero output (also covers the scalar-loss element if present)
    cudaMemsetAsync(d_out, 0, (size_t)out_size * sizeof(float), 0);

    zero_route_kernel<<<1, 32>>>();
    count_kernel<<<(NKROWS + 255) / 256, 256>>>(idx);
    scan_kernel<<<1, 32>>>();
    place_kernel<<<(NKROWS + 255) / 256, 256>>>(idx);

    convert_x_kernel<<<(NTOK * DMODEL / 4 + 255) / 256, 256>>>(x);
    dim3 wgrid(DMODEL / 32, DMODEL / 32, NEXP);
    convert_w_kernel<<<wgrid, dim3(32, 8)>>>(W);

    dim3 ggrid(DMODEL / BN, NKROWS / BM, NEXP);   // (4, 256, 8); most exit early
    moe_gemm_kernel<<<ggrid, 256>>>();

    int cthreads = NTOK * (DMODEL / 4);
    combine_kernel<<<(cthreads + 255) / 256, 256>>>(prob, idx, bias, out);
}

// round 6
// speedup vs baseline: 3.6854x; 2.6970x over previous
#include <cuda_runtime.h>
#include <cuda_fp16.h>
#include <cstdint>

// ---------------- problem constants ----------------------------------------
#define DMODEL 512
#define NEXP   8
#define NTOK   16384
#define NKROWS 32768          // NTOK * top_k
#define BM     128
#define BN     128
#define BKc    32             // fp16 k per chunk
#define NCHUNK (DMODEL / BKc) // 16
#define ASTR   40             // smem row stride in fp16 elems (32 + 8 pad = 80B)
#define STAGES 3
#define STAGE_BYTES (BM * ASTR * 2)   // 10240 per matrix per stage

// ---------------- static device scratch -------------------------------------
__device__ int g_cnt[NEXP], g_cur[NEXP], g_off[NEXP + 1];
__device__ int g_tok[NKROWS];                      // compact row -> token
__device__ int g_row[NKROWS];                      // (token,slot) -> compact row
__device__ __half g_xf[NTOK * DMODEL];             // x in fp16
__device__ __half g_Bt[NEXP * DMODEL * DMODEL];    // W^T in fp16 [e][n][k]
__device__ float  g_y[(size_t)NKROWS * DMODEL];    // raw expert outputs

// ---------------- helpers ----------------------------------------------------
__device__ __forceinline__ uint32_t smem_u32(const void* p) {
    uint32_t a;
    asm("{ .reg .u64 t; cvta.to.shared.u64 t, %1; cvt.u32.u64 %0, t; }"
        : "=r"(a) : "l"(p));
    return a;
}
__device__ __forceinline__ void cp16(uint32_t dst, const void* src) {
    asm volatile("cp.async.ca.shared.global [%0], [%1], 16;"
                 :: "r"(dst), "l"(src) : "memory");
}
#define CP_COMMIT() asm volatile("cp.async.commit_group;" ::: "memory")
#define CP_WAIT1()  asm volatile("cp.async.wait_group 1;" ::: "memory")
#define CP_WAIT0()  asm volatile("cp.async.wait_group 0;" ::: "memory")

__device__ __forceinline__ void ldsm_x4(uint32_t* r, uint32_t addr) {
    asm volatile("ldmatrix.sync.aligned.m8n8.x4.shared.b16 {%0,%1,%2,%3}, [%4];"
                 : "=r"(r[0]), "=r"(r[1]), "=r"(r[2]), "=r"(r[3]) : "r"(addr));
}
__device__ __forceinline__ void mma16816(float* c, const uint32_t* a,
                                         uint32_t b0, uint32_t b1) {
    asm volatile(
        "mma.sync.aligned.m16n8k16.row.col.f32.f16.f16.f32 "
        "{%0,%1,%2,%3}, {%4,%5,%6,%7}, {%8,%9}, {%0,%1,%2,%3};"
        : "+f"(c[0]), "+f"(c[1]), "+f"(c[2]), "+f"(c[3])
        : "r"(a[0]), "r"(a[1]), "r"(a[2]), "r"(a[3]), "r"(b0), "r"(b1));
}

// ---------------- routing (block-aggregated atomics) -------------------------
__global__ void zero_route_kernel() {
    if (threadIdx.x < NEXP) { g_cnt[threadIdx.x] = 0; g_cur[threadIdx.x] = 0; }
}
__global__ void count_kernel(const int* __restrict__ idx) {
    __shared__ int sc[NEXP];
    if (threadIdx.x < NEXP) sc[threadIdx.x] = 0;
    __syncthreads();
    int i = blockIdx.x * blockDim.x + threadIdx.x;
    if (i < NKROWS) atomicAdd(&sc[idx[i]], 1);
    __syncthreads();
    if (threadIdx.x < NEXP && sc[threadIdx.x])
        atomicAdd(&g_cnt[threadIdx.x], sc[threadIdx.x]);
}
__global__ void scan_kernel() {
    if (threadIdx.x == 0) {
        int acc = 0;
        for (int e = 0; e < NEXP; e++) { g_off[e] = acc; acc += g_cnt[e]; }
        g_off[NEXP] = acc;
    }
}
__global__ void place_kernel(const int* __restrict__ idx) {
    __shared__ int sCur[NEXP], sBase[NEXP];
    if (threadIdx.x < NEXP) sCur[threadIdx.x] = 0;
    __syncthreads();
    int i = blockIdx.x * blockDim.x + threadIdx.x;
    int e = -1, lp = 0;
    if (i < NKROWS) { e = idx[i]; lp = atomicAdd(&sCur[e], 1); }
    __syncthreads();
    if (threadIdx.x < NEXP)
        sBase[threadIdx.x] = sCur[threadIdx.x] ?
            atomicAdd(&g_cur[threadIdx.x], sCur[threadIdx.x]) : 0;
    __syncthreads();
    if (i < NKROWS) {
        int pos = g_off[e] + sBase[e] + lp;
        g_tok[pos] = i >> 1;
        g_row[i] = pos;
    }
}

// ---------------- conversions ------------------------------------------------
__global__ void convert_x_kernel(const float* __restrict__ x) {
    int i = blockIdx.x * blockDim.x + threadIdx.x;   // per 8 floats
    if (i >= NTOK * DMODEL / 8) return;
    float4 v0 = ((const float4*)x)[2 * i];
    float4 v1 = ((const float4*)x)[2 * i + 1];
    __half2* dst = (__half2*)(g_xf + 8 * (size_t)i);
    dst[0] = __floats2half2_rn(v0.x, v0.y);
    dst[1] = __floats2half2_rn(v0.z, v0.w);
    dst[2] = __floats2half2_rn(v1.x, v1.y);
    dst[3] = __floats2half2_rn(v1.z, v1.w);
}
__global__ void convert_w_kernel(const float* __restrict__ W) {
    __shared__ float tile[32][33];
    int e = blockIdx.z, k0 = blockIdx.x * 32, n0 = blockIdx.y * 32;
    int tx = threadIdx.x, ty = threadIdx.y;
    const float* Wb = W + (size_t)e * DMODEL * DMODEL;
    for (int r = ty; r < 32; r += 8)
        tile[r][tx] = Wb[(size_t)(k0 + r) * DMODEL + n0 + tx];
    __syncthreads();
    __half* Be = g_Bt + (size_t)e * DMODEL * DMODEL;
    for (int r = ty; r < 32; r += 8)
        Be[(size_t)(n0 + r) * DMODEL + k0 + tx] = __float2half_rn(tile[tx][r]);
}

// ---------------- grouped GEMM via mma.sync (fp16, cp.async pipeline) --------
__global__ __launch_bounds__(256, 2)
void moe_gemm_kernel() {
    const int e = blockIdx.z;
    const int r0 = g_off[e], r1 = g_off[e + 1];
    const int m0 = r0 + blockIdx.y * BM;
    if (m0 >= r1) return;
    const int n0 = blockIdx.x * BN;

    extern __shared__ __half dsm[];
    __half* sA = dsm;                              // [STAGES][BM*ASTR]
    __half* sB = dsm + STAGES * BM * ASTR;         // [STAGES][BN*ASTR]
    __shared__ int sTok[BM];

    const int tid  = threadIdx.x;
    const int wid  = tid >> 5;
    const int lane = tid & 31;
    const int wm   = wid & 3;     // 4 M slices of 32 rows
    const int wn   = wid >> 2;    // 2 N slices of 64 cols

    if (tid < BM) {
        int r = m0 + tid;
        sTok[tid] = (r < r1) ? g_tok[r] : g_tok[m0];
    }
    __syncthreads();

    // global-load mapping: each thread owns 32B of one row per matrix per chunk
    const int lr = tid >> 1, lh = tid & 1;
    const __half* Arow = g_xf + (size_t)sTok[lr] * DMODEL + lh * 16;
    const __half* Brow = g_Bt + ((size_t)e * DMODEL + n0 + lr) * DMODEL + lh * 16;
    const uint32_t sAa = smem_u32(sA) + (uint32_t)(lr * 80 + lh * 32);
    const uint32_t sBa = smem_u32(sB) + (uint32_t)(lr * 80 + lh * 32);

    auto load_stage = [&](int t) {
        int buf = t % STAGES;
        int kc = t * BKc;
        uint32_t da = sAa + buf * STAGE_BYTES;
        uint32_t db = sBa + buf * STAGE_BYTES;
        cp16(da,      Arow + kc);
        cp16(da + 16, Arow + kc + 8);
        cp16(db,      Brow + kc);
        cp16(db + 16, Brow + kc + 8);
        CP_COMMIT();
    };

    float acc[2][8][4];
#pragma unroll
    for (int i = 0; i < 2; i++)
#pragma unroll
        for (int j = 0; j < 8; j++)
#pragma unroll
            for (int q = 0; q < 4; q++) acc[i][j][q] = 0.0f;

    // ldmatrix lane addressing (byte offsets within a stage)
    const int aRow = wm * 32 + (lane & 7) + ((lane >> 3) & 1) * 8;
    const int aK   = ((lane >> 4) & 1) * 8;
    const int bRow = wn * 64 + (lane & 7) + ((lane >> 4) & 1) * 8;
    const int bK   = ((lane >> 3) & 1) * 8;
    const uint32_t aLd = smem_u32(sA) + (uint32_t)(aRow * 80 + aK * 2);
    const uint32_t bLd = smem_u32(sB) + (uint32_t)(bRow * 80 + bK * 2);

    load_stage(0);
    load_stage(1);

    for (int t = 0; t < NCHUNK; t++) {
        const int buf = t % STAGES;
        // Drain rule: while more loads are outstanding, the group we need is
        // the second-newest -> wait_group 1. On the LAST iteration the group
        // we need IS the newest -> must wait_group 0 (this was the R5 bug).
        if (t < NCHUNK - 1) { CP_WAIT1(); } else { CP_WAIT0(); }
        __syncthreads();
        if (t + 2 < NCHUNK) load_stage(t + 2);

        const uint32_t aBase = aLd + buf * STAGE_BYTES;
        const uint32_t bBase = bLd + buf * STAGE_BYTES;
#pragma unroll
        for (int k16 = 0; k16 < 2; k16++) {
            uint32_t a[2][4];
#pragma unroll
            for (int mt = 0; mt < 2; mt++)
                ldsm_x4(a[mt], aBase + mt * 16 * 80 + k16 * 32);
            uint32_t b[4][4];
#pragma unroll
            for (int nt2 = 0; nt2 < 4; nt2++)
                ldsm_x4(b[nt2], bBase + nt2 * 16 * 80 + k16 * 32);
#pragma unroll
            for (int mt = 0; mt < 2; mt++)
#pragma unroll
                for (int nt2 = 0; nt2 < 4; nt2++) {
                    mma16816(acc[mt][2 * nt2 + 0], a[mt], b[nt2][0], b[nt2][1]);
                    mma16816(acc[mt][2 * nt2 + 1], a[mt], b[nt2][2], b[nt2][3]);
                }
        }
    }

    // ---- epilogue: fragments -> g_y (plain stores) ----
    const int qrow = lane >> 2;
    const int qcol = 2 * (lane & 3);
#pragma unroll
    for (int mt = 0; mt < 2; mt++) {
        int rbase = m0 + wm * 32 + mt * 16 + qrow;
#pragma unroll
        for (int half = 0; half < 2; half++) {
            int grow = rbase + half * 8;
            if (grow < r1) {
                float* yr = g_y + (size_t)grow * DMODEL + n0 + wn * 64 + qcol;
#pragma unroll
                for (int nt = 0; nt < 8; nt++) {
                    float2 v = make_float2(acc[mt][nt][2 * half],
                                           acc[mt][nt][2 * half + 1]);
                    *(float2*)(yr + nt * 8) = v;
                }
            }
        }
    }
}

// ---------------- combine: out[n] = sum_k p * (y[row] + b[e]) ----------------
__global__ void combine_kernel(const float* __restrict__ prob,
                               const int* __restrict__ idx,
                               const float* __restrict__ bias,
                               float* __restrict__ out) {
    int i = blockIdx.x * blockDim.x + threadIdx.x;   // over NTOK * 128
    if (i >= NTOK * (DMODEL / 4)) return;
    int n = i >> 7;
    int c4 = i & 127;
    int e0 = idx[2 * n], e1 = idx[2 * n + 1];
    float p0 = prob[2 * n], p1 = prob[2 * n + 1];
    int rr0 = g_row[2 * n], rr1 = g_row[2 * n + 1];
    float4 y0 = ((const float4*)g_y)[(size_t)rr0 * 128 + c4];
    float4 y1 = ((const float4*)g_y)[(size_t)rr1 * 128 + c4];
    float4 b0 = ((const float4*)(bias + (size_t)e0 * DMODEL))[c4];
    float4 b1 = ((const float4*)(bias + (size_t)e1 * DMODEL))[c4];
    float4 o;
    o.x = p0 * (y0.x + b0.x) + p1 * (y1.x + b1.x);
    o.y = p0 * (y0.y + b0.y) + p1 * (y1.y + b1.y);
    o.z = p0 * (y0.z + b0.z) + p1 * (y1.z + b1.z);
    o.w = p0 * (y0.w + b0.w) + p1 * (y1.w + b1.w);
    ((float4*)out)[(size_t)n * 128 + c4] = o;
}

// ---------------- launch -----------------------------------------------------
extern "C" void kernel_launch(void* const* d_in, const int* in_sizes, int n_in,
                              void* d_out, int out_size) {
    const float* x    = (const float*)d_in[0];
    const float* prob = (const float*)d_in[1];
    const int*   idx  = (const int*)d_in[2];
    const float* W    = (const float*)d_in[3];
    const float* bias = (const float*)d_in[4];
    float* out = (float*)d_out;

    static int smem_set = 0;
    const int SMEMB = STAGES * (BM * ASTR + BN * ASTR) * 2;  // 61440
    if (!smem_set) {
        cudaFuncSetAttribute(moe_gemm_kernel,
                             cudaFuncAttributeMaxDynamicSharedMemorySize, SMEMB);
        smem_set = 1;
    }

    // zero output (also covers the scalar-loss element if present)
    cudaMemsetAsync(d_out, 0, (size_t)out_size * sizeof(float), 0);

    zero_route_kernel<<<1, 32>>>();
    count_kernel<<<(NKROWS + 255) / 256, 256>>>(idx);
    scan_kernel<<<1, 32>>>();
    place_kernel<<<(NKROWS + 255) / 256, 256>>>(idx);

    convert_x_kernel<<<(NTOK * DMODEL / 8 + 255) / 256, 256>>>(x);
    dim3 wgrid(DMODEL / 32, DMODEL / 32, NEXP);
    convert_w_kernel<<<wgrid, dim3(32, 8)>>>(W);

    dim3 ggrid(DMODEL / BN, NKROWS / BM, NEXP);   // (4, 256, 8); most exit early
    moe_gemm_kernel<<<ggrid, 256, SMEMB>>>();

    int cthreads = NTOK * (DMODEL / 4);
    combine_kernel<<<(cthreads + 255) / 256, 256>>>(prob, idx, bias, out);
}

// round 7
// speedup vs baseline: 3.8794x; 1.0526x over previous
#include <cuda_runtime.h>
#include <cuda_fp16.h>
#include <cstdint>

// ---------------- problem constants ----------------------------------------
#define DMODEL 512
#define NEXP   8
#define NTOK   16384
#define NKROWS 32768          // NTOK * top_k
#define BM     128
#define BN     128
#define BKc    32             // fp16 k per chunk
#define NCHUNK (DMODEL / BKc) // 16
#define ASTR   40             // smem row stride in fp16 elems (32 + 8 pad = 80B)
#define STAGES 3
#define STAGE_BYTES (BM * ASTR * 2)   // 10240 per matrix per stage

// ---------------- static device scratch -------------------------------------
__device__ int g_cnt[NEXP], g_cur[NEXP], g_off[NEXP + 1];
__device__ int g_tok[NKROWS];                      // compact row -> token
__device__ int g_row[NKROWS];                      // (token,slot) -> compact row
__device__ __half g_xf[NTOK * DMODEL];             // x in fp16
__device__ __half g_Bt[NEXP * DMODEL * DMODEL];    // W^T in fp16 [e][n][k]
__device__ __half g_y[(size_t)NKROWS * DMODEL];    // raw expert outputs (fp16)

// ---------------- helpers ----------------------------------------------------
__device__ __forceinline__ uint32_t smem_u32(const void* p) {
    uint32_t a;
    asm("{ .reg .u64 t; cvta.to.shared.u64 t, %1; cvt.u32.u64 %0, t; }"
        : "=r"(a) : "l"(p));
    return a;
}
__device__ __forceinline__ void cp16(uint32_t dst, const void* src) {
    asm volatile("cp.async.ca.shared.global [%0], [%1], 16;"
                 :: "r"(dst), "l"(src) : "memory");
}
#define CP_COMMIT() asm volatile("cp.async.commit_group;" ::: "memory")
#define CP_WAIT1()  asm volatile("cp.async.wait_group 1;" ::: "memory")
#define CP_WAIT0()  asm volatile("cp.async.wait_group 0;" ::: "memory")

__device__ __forceinline__ void ldsm_x4(uint32_t* r, uint32_t addr) {
    asm volatile("ldmatrix.sync.aligned.m8n8.x4.shared.b16 {%0,%1,%2,%3}, [%4];"
                 : "=r"(r[0]), "=r"(r[1]), "=r"(r[2]), "=r"(r[3]) : "r"(addr));
}
__device__ __forceinline__ void mma16816(float* c, const uint32_t* a,
                                         uint32_t b0, uint32_t b1) {
    asm volatile(
        "mma.sync.aligned.m16n8k16.row.col.f32.f16.f16.f32 "
        "{%0,%1,%2,%3}, {%4,%5,%6,%7}, {%8,%9}, {%0,%1,%2,%3};"
        : "+f"(c[0]), "+f"(c[1]), "+f"(c[2]), "+f"(c[3])
        : "r"(a[0]), "r"(a[1]), "r"(a[2]), "r"(a[3]), "r"(b0), "r"(b1));
}

// ---------------- routing (block-aggregated atomics) -------------------------
__global__ void zero_route_kernel() {
    if (threadIdx.x < NEXP) { g_cnt[threadIdx.x] = 0; g_cur[threadIdx.x] = 0; }
}
__global__ void count_kernel(const int* __restrict__ idx) {
    __shared__ int sc[NEXP];
    if (threadIdx.x < NEXP) sc[threadIdx.x] = 0;
    __syncthreads();
    int i = blockIdx.x * blockDim.x + threadIdx.x;
    if (i < NKROWS) atomicAdd(&sc[idx[i]], 1);
    __syncthreads();
    if (threadIdx.x < NEXP && sc[threadIdx.x])
        atomicAdd(&g_cnt[threadIdx.x], sc[threadIdx.x]);
}
__global__ void scan_kernel() {
    if (threadIdx.x == 0) {
        int acc = 0;
        for (int e = 0; e < NEXP; e++) { g_off[e] = acc; acc += g_cnt[e]; }
        g_off[NEXP] = acc;
    }
}
__global__ void place_kernel(const int* __restrict__ idx) {
    __shared__ int sCur[NEXP], sBase[NEXP];
    if (threadIdx.x < NEXP) sCur[threadIdx.x] = 0;
    __syncthreads();
    int i = blockIdx.x * blockDim.x + threadIdx.x;
    int e = -1, lp = 0;
    if (i < NKROWS) { e = idx[i]; lp = atomicAdd(&sCur[e], 1); }
    __syncthreads();
    if (threadIdx.x < NEXP)
        sBase[threadIdx.x] = sCur[threadIdx.x] ?
            atomicAdd(&g_cur[threadIdx.x], sCur[threadIdx.x]) : 0;
    __syncthreads();
    if (i < NKROWS) {
        int pos = g_off[e] + sBase[e] + lp;
        g_tok[pos] = i >> 1;
        g_row[i] = pos;
    }
}

// ---------------- conversions ------------------------------------------------
__global__ void convert_x_kernel(const float* __restrict__ x) {
    int i = blockIdx.x * blockDim.x + threadIdx.x;   // per 8 floats
    if (i >= NTOK * DMODEL / 8) return;
    float4 v0 = ((const float4*)x)[2 * i];
    float4 v1 = ((const float4*)x)[2 * i + 1];
    __half2* dst = (__half2*)(g_xf + 8 * (size_t)i);
    dst[0] = __floats2half2_rn(v0.x, v0.y);
    dst[1] = __floats2half2_rn(v0.z, v0.w);
    dst[2] = __floats2half2_rn(v1.x, v1.y);
    dst[3] = __floats2half2_rn(v1.z, v1.w);
}
__global__ void convert_w_kernel(const float* __restrict__ W) {
    __shared__ float tile[32][33];
    int e = blockIdx.z, k0 = blockIdx.x * 32, n0 = blockIdx.y * 32;
    int tx = threadIdx.x, ty = threadIdx.y;
    const float* Wb = W + (size_t)e * DMODEL * DMODEL;
    for (int r = ty; r < 32; r += 8)
        tile[r][tx] = Wb[(size_t)(k0 + r) * DMODEL + n0 + tx];
    __syncthreads();
    __half* Be = g_Bt + (size_t)e * DMODEL * DMODEL;
    for (int r = ty; r < 32; r += 8)
        Be[(size_t)(n0 + r) * DMODEL + k0 + tx] = __float2half_rn(tile[tx][r]);
}

// ---------------- grouped GEMM via mma.sync (fp16, cp.async pipeline) --------
__global__ __launch_bounds__(256, 2)
void moe_gemm_kernel() {
    const int e = blockIdx.z;
    const int r0 = g_off[e], r1 = g_off[e + 1];
    const int m0 = r0 + blockIdx.y * BM;
    if (m0 >= r1) return;
    const int n0 = blockIdx.x * BN;

    extern __shared__ __half dsm[];
    __half* sA = dsm;                              // [STAGES][BM*ASTR]
    __half* sB = dsm + STAGES * BM * ASTR;         // [STAGES][BN*ASTR]
    __shared__ int sTok[BM];

    const int tid  = threadIdx.x;
    const int wid  = tid >> 5;
    const int lane = tid & 31;
    const int wm   = wid & 3;     // 4 M slices of 32 rows
    const int wn   = wid >> 2;    // 2 N slices of 64 cols

    if (tid < BM) {
        int r = m0 + tid;
        sTok[tid] = (r < r1) ? g_tok[r] : g_tok[m0];
    }
    __syncthreads();

    // global-load mapping: each thread owns 32B of one row per matrix per chunk
    const int lr = tid >> 1, lh = tid & 1;
    const __half* Arow = g_xf + (size_t)sTok[lr] * DMODEL + lh * 16;
    const __half* Brow = g_Bt + ((size_t)e * DMODEL + n0 + lr) * DMODEL + lh * 16;
    const uint32_t sAa = smem_u32(sA) + (uint32_t)(lr * 80 + lh * 32);
    const uint32_t sBa = smem_u32(sB) + (uint32_t)(lr * 80 + lh * 32);

    auto load_stage = [&](int t) {
        int buf = t % STAGES;
        int kc = t * BKc;
        uint32_t da = sAa + buf * STAGE_BYTES;
        uint32_t db = sBa + buf * STAGE_BYTES;
        cp16(da,      Arow + kc);
        cp16(da + 16, Arow + kc + 8);
        cp16(db,      Brow + kc);
        cp16(db + 16, Brow + kc + 8);
        CP_COMMIT();
    };

    float acc[2][8][4];
#pragma unroll
    for (int i = 0; i < 2; i++)
#pragma unroll
        for (int j = 0; j < 8; j++)
#pragma unroll
            for (int q = 0; q < 4; q++) acc[i][j][q] = 0.0f;

    // ldmatrix lane addressing (byte offsets within a stage)
    const int aRow = wm * 32 + (lane & 7) + ((lane >> 3) & 1) * 8;
    const int aK   = ((lane >> 4) & 1) * 8;
    const int bRow = wn * 64 + (lane & 7) + ((lane >> 4) & 1) * 8;
    const int bK   = ((lane >> 3) & 1) * 8;
    const uint32_t aLd = smem_u32(sA) + (uint32_t)(aRow * 80 + aK * 2);
    const uint32_t bLd = smem_u32(sB) + (uint32_t)(bRow * 80 + bK * 2);

    load_stage(0);
    load_stage(1);

    for (int t = 0; t < NCHUNK; t++) {
        const int buf = t % STAGES;
        // Drain rule: last iteration's group is the newest -> wait_group 0.
        if (t < NCHUNK - 1) { CP_WAIT1(); } else { CP_WAIT0(); }
        __syncthreads();
        if (t + 2 < NCHUNK) load_stage(t + 2);

        const uint32_t aBase = aLd + buf * STAGE_BYTES;
        const uint32_t bBase = bLd + buf * STAGE_BYTES;
#pragma unroll
        for (int k16 = 0; k16 < 2; k16++) {
            uint32_t a[2][4];
#pragma unroll
            for (int mt = 0; mt < 2; mt++)
                ldsm_x4(a[mt], aBase + mt * 16 * 80 + k16 * 32);
            uint32_t b[4][4];
#pragma unroll
            for (int nt2 = 0; nt2 < 4; nt2++)
                ldsm_x4(b[nt2], bBase + nt2 * 16 * 80 + k16 * 32);
#pragma unroll
            for (int mt = 0; mt < 2; mt++)
#pragma unroll
                for (int nt2 = 0; nt2 < 4; nt2++) {
                    mma16816(acc[mt][2 * nt2 + 0], a[mt], b[nt2][0], b[nt2][1]);
                    mma16816(acc[mt][2 * nt2 + 1], a[mt], b[nt2][2], b[nt2][3]);
                }
        }
    }

    // ---- epilogue: fragments -> g_y as fp16 (plain stores) ----
    const int qrow = lane >> 2;
    const int qcol = 2 * (lane & 3);
#pragma unroll
    for (int mt = 0; mt < 2; mt++) {
        int rbase = m0 + wm * 32 + mt * 16 + qrow;
#pragma unroll
        for (int half = 0; half < 2; half++) {
            int grow = rbase + half * 8;
            if (grow < r1) {
                __half* yr = g_y + (size_t)grow * DMODEL + n0 + wn * 64 + qcol;
#pragma unroll
                for (int nt = 0; nt < 8; nt++) {
                    __half2 hv = __floats2half2_rn(acc[mt][nt][2 * half],
                                                   acc[mt][nt][2 * half + 1]);
                    *(__half2*)(yr + nt * 8) = hv;
                }
            }
        }
    }
}

// ---------------- combine: out[n] = sum_k p * (y[row] + b[e]) ----------------
__global__ void combine_kernel(const float* __restrict__ prob,
                               const int* __restrict__ idx,
                               const float* __restrict__ bias,
                               float* __restrict__ out) {
    int i = blockIdx.x * blockDim.x + threadIdx.x;   // over NTOK * 64 (8 cols each)
    if (i >= NTOK * (DMODEL / 8)) return;
    int n  = i >> 6;
    int c8 = i & 63;                                  // 8-col group
    int e0 = idx[2 * n], e1 = idx[2 * n + 1];
    float p0 = prob[2 * n], p1 = prob[2 * n + 1];
    int rr0 = g_row[2 * n], rr1 = g_row[2 * n + 1];

    uint4 u0 = ((const uint4*)g_y)[(size_t)rr0 * (DMODEL / 8) + c8];
    uint4 u1 = ((const uint4*)g_y)[(size_t)rr1 * (DMODEL / 8) + c8];
    const __half2* h0 = (const __half2*)&u0;
    const __half2* h1 = (const __half2*)&u1;

    const float4* bb0 = (const float4*)(bias + (size_t)e0 * DMODEL) + 2 * c8;
    const float4* bb1 = (const float4*)(bias + (size_t)e1 * DMODEL) + 2 * c8;
    float4* op = (float4*)out + (size_t)n * (DMODEL / 4) + 2 * c8;

#pragma unroll
    for (int q = 0; q < 2; q++) {
        float2 a0 = __half22float2(h0[2 * q + 0]);
        float2 a1 = __half22float2(h0[2 * q + 1]);
        float2 c0 = __half22float2(h1[2 * q + 0]);
        float2 c1 = __half22float2(h1[2 * q + 1]);
        float4 b0 = bb0[q];
        float4 b1 = bb1[q];
        float4 o;
        o.x = p0 * (a0.x + b0.x) + p1 * (c0.x + b1.x);
        o.y = p0 * (a0.y + b0.y) + p1 * (c0.y + b1.y);
        o.z = p0 * (a1.x + b0.z) + p1 * (c1.x + b1.z);
        o.w = p0 * (a1.y + b0.w) + p1 * (c1.y + b1.w);
        op[q] = o;
    }
}

// ---------------- launch -----------------------------------------------------
extern "C" void kernel_launch(void* const* d_in, const int* in_sizes, int n_in,
                              void* d_out, int out_size) {
    const float* x    = (const float*)d_in[0];
    const float* prob = (const float*)d_in[1];
    const int*   idx  = (const int*)d_in[2];
    const float* W    = (const float*)d_in[3];
    const float* bias = (const float*)d_in[4];

    static int smem_set = 0;
    const int SMEMB = STAGES * (BM * ASTR + BN * ASTR) * 2;  // 61440
    if (!smem_set) {
        cudaFuncSetAttribute(moe_gemm_kernel,
                             cudaFuncAttributeMaxDynamicSharedMemorySize, SMEMB);
        smem_set = 1;
    }

    // combine_kernel writes all NTOK*DMODEL output elements; only the tail
    // (scalar loss etc.) needs zeroing.
    if (out_size > NTOK * DMODEL) {
        cudaMemsetAsync((float*)d_out + NTOK * DMODEL, 0,
                        (size_t)(out_size - NTOK * DMODEL) * sizeof(float), 0);
    }

    zero_route_kernel<<<1, 32>>>();
    count_kernel<<<(NKROWS + 255) / 256, 256>>>(idx);
    scan_kernel<<<1, 32>>>();
    place_kernel<<<(NKROWS + 255) / 256, 256>>>(idx);

    convert_x_kernel<<<(NTOK * DMODEL / 8 + 255) / 256, 256>>>(x);
    dim3 wgrid(DMODEL / 32, DMODEL / 32, NEXP);
    convert_w_kernel<<<wgrid, dim3(32, 8)>>>(W);

    dim3 ggrid(DMODEL / BN, NKROWS / BM, NEXP);   // (4, 256, 8); most exit early
    moe_gemm_kernel<<<ggrid, 256, SMEMB>>>();

    int cthreads = NTOK * (DMODEL / 8);
    combine_kernel<<<(cthreads + 255) / 256, 256>>>(prob, idx, bias, (float*)d_out);
}

// round 8
// speedup vs baseline: 4.3104x; 1.1111x over previous
#include <cuda_runtime.h>
#include <cuda_fp16.h>
#include <cstdint>

// ---------------- problem constants ----------------------------------------
#define DMODEL 512
#define NEXP   8
#define NTOK   16384
#define NKROWS 32768          // NTOK * top_k
#define BM     128
#define BN     128
#define BKc    32             // fp16 k per chunk
#define NCHUNK (DMODEL / BKc) // 16
#define ASTR   40             // smem row stride in fp16 elems (32 + 8 pad = 80B)
#define STAGES 3
#define STAGE_BYTES (BM * ASTR * 2)   // 10240 per matrix per stage

#define NBLK_ROUTE (NKROWS / 256)     // 128 routing blocks
#define NBLK_CONVX (NTOK * DMODEL / 8 / 256)  // 4096
#define NBLK_CONVW (NEXP * (DMODEL / 32) * (DMODEL / 32))  // 2048

// ---------------- static device scratch -------------------------------------
__device__ int g_blkcnt[NBLK_ROUTE * NEXP];        // per-block expert histograms
__device__ int g_off[NEXP + 1];
__device__ int g_tok[NKROWS];                      // compact row -> token
__device__ int g_row[NKROWS];                      // (token,slot) -> compact row
__device__ __half g_xf[NTOK * DMODEL];             // x in fp16
__device__ __half g_Bt[NEXP * DMODEL * DMODEL];    // W^T in fp16 [e][n][k]
__device__ __half g_y[(size_t)NKROWS * DMODEL];    // expert outputs + bias (fp16)

// ---------------- helpers ----------------------------------------------------
__device__ __forceinline__ uint32_t smem_u32(const void* p) {
    uint32_t a;
    asm("{ .reg .u64 t; cvta.to.shared.u64 t, %1; cvt.u32.u64 %0, t; }"
        : "=r"(a) : "l"(p));
    return a;
}
__device__ __forceinline__ void cp16(uint32_t dst, const void* src) {
    asm volatile("cp.async.ca.shared.global [%0], [%1], 16;"
                 :: "r"(dst), "l"(src) : "memory");
}
#define CP_COMMIT() asm volatile("cp.async.commit_group;" ::: "memory")
#define CP_WAIT1()  asm volatile("cp.async.wait_group 1;" ::: "memory")
#define CP_WAIT0()  asm volatile("cp.async.wait_group 0;" ::: "memory")

__device__ __forceinline__ void ldsm_x4(uint32_t* r, uint32_t addr) {
    asm volatile("ldmatrix.sync.aligned.m8n8.x4.shared.b16 {%0,%1,%2,%3}, [%4];"
                 : "=r"(r[0]), "=r"(r[1]), "=r"(r[2]), "=r"(r[3]) : "r"(addr));
}
__device__ __forceinline__ void mma16816(float* c, const uint32_t* a,
                                         uint32_t b0, uint32_t b1) {
    asm volatile(
        "mma.sync.aligned.m16n8k16.row.col.f32.f16.f16.f32 "
        "{%0,%1,%2,%3}, {%4,%5,%6,%7}, {%8,%9}, {%0,%1,%2,%3};"
        : "+f"(c[0]), "+f"(c[1]), "+f"(c[2]), "+f"(c[3])
        : "r"(a[0]), "r"(a[1]), "r"(a[2]), "r"(a[3]), "r"(b0), "r"(b1));
}

// ---------------- K1: per-block histograms + x fp16 convert ------------------
__global__ void k1_count_convx(const int* __restrict__ idx,
                               const float* __restrict__ x) {
    const int b = blockIdx.x;
    const int t = threadIdx.x;
    if (b < NBLK_ROUTE) {
        __shared__ int sc[NEXP];
        if (t < NEXP) sc[t] = 0;
        __syncthreads();
        atomicAdd(&sc[idx[b * 256 + t]], 1);
        __syncthreads();
        if (t < NEXP) g_blkcnt[b * NEXP + t] = sc[t];
    } else {
        int i = (b - NBLK_ROUTE) * 256 + t;          // per 8 floats
        float4 v0 = ((const float4*)x)[2 * i];
        float4 v1 = ((const float4*)x)[2 * i + 1];
        __half2* dst = (__half2*)(g_xf + 8 * (size_t)i);
        dst[0] = __floats2half2_rn(v0.x, v0.y);
        dst[1] = __floats2half2_rn(v0.z, v0.w);
        dst[2] = __floats2half2_rn(v1.x, v1.y);
        dst[3] = __floats2half2_rn(v1.z, v1.w);
    }
}

// ---------------- K2: place tokens + W transpose/convert ---------------------
__global__ void k2_place_convw(const int* __restrict__ idx,
                               const float* __restrict__ W) {
    const int b = blockIdx.x;
    const int t = threadIdx.x;
    if (b < NBLK_ROUTE) {
        __shared__ int cnt[NBLK_ROUTE * NEXP];   // 4 KB
        __shared__ int stot[NEXP], sbase[NEXP], soff[NEXP + 1], scur[NEXP];
        for (int j = t; j < NBLK_ROUTE * NEXP; j += 256) cnt[j] = g_blkcnt[j];
        if (t < NEXP) scur[t] = 0;
        __syncthreads();
        if (t < NEXP) {
            int tot = 0, bb = 0;
            for (int blk = 0; blk < NBLK_ROUTE; blk++) {
                int c = cnt[blk * NEXP + t];
                if (blk < b) bb += c;
                tot += c;
            }
            stot[t] = tot;
            sbase[t] = bb;
        }
        __syncthreads();
        if (t == 0) {
            int acc = 0;
            for (int e2 = 0; e2 < NEXP; e2++) { soff[e2] = acc; acc += stot[e2]; }
            soff[NEXP] = acc;
        }
        __syncthreads();
        int i = b * 256 + t;
        int e = idx[i];
        int lp = atomicAdd(&scur[e], 1);
        int pos = soff[e] + sbase[e] + lp;
        g_tok[pos] = i >> 1;
        g_row[i] = pos;
        if (b == 0 && t <= NEXP) g_off[t] = soff[t];
    } else {
        // W transpose + fp16 convert: one 32x32 tile per block
        __shared__ float tile[32][33];
        int w = b - NBLK_ROUTE;
        int e = w >> 8;                   // 256 tiles per expert
        int k0 = (w & 15) * 32;
        int n0 = ((w >> 4) & 15) * 32;
        int tx = t & 31, ty = t >> 5;     // 32 x 8
        const float* Wb = W + (size_t)e * DMODEL * DMODEL;
        for (int r = ty; r < 32; r += 8)
            tile[r][tx] = Wb[(size_t)(k0 + r) * DMODEL + n0 + tx];
        __syncthreads();
        __half* Be = g_Bt + (size_t)e * DMODEL * DMODEL;
        for (int r = ty; r < 32; r += 8)
            Be[(size_t)(n0 + r) * DMODEL + k0 + tx] = __float2half_rn(tile[tx][r]);
    }
}

// ---------------- grouped GEMM via mma.sync (fp16, cp.async pipeline) --------
__global__ __launch_bounds__(256, 2)
void moe_gemm_kernel(const float* __restrict__ bias) {
    const int e = blockIdx.z;
    const int r0 = g_off[e], r1 = g_off[e + 1];
    const int m0 = r0 + blockIdx.y * BM;
    if (m0 >= r1) return;
    const int n0 = blockIdx.x * BN;

    extern __shared__ __half dsm[];
    __half* sA = dsm;                              // [STAGES][BM*ASTR]
    __half* sB = dsm + STAGES * BM * ASTR;         // [STAGES][BN*ASTR]
    __shared__ int sTok[BM];

    const int tid  = threadIdx.x;
    const int wid  = tid >> 5;
    const int lane = tid & 31;
    const int wm   = wid & 3;     // 4 M slices of 32 rows
    const int wn   = wid >> 2;    // 2 N slices of 64 cols

    if (tid < BM) {
        int r = m0 + tid;
        sTok[tid] = (r < r1) ? g_tok[r] : g_tok[m0];
    }
    __syncthreads();

    // global-load mapping: each thread owns 32B of one row per matrix per chunk
    const int lr = tid >> 1, lh = tid & 1;
    const __half* Arow = g_xf + (size_t)sTok[lr] * DMODEL + lh * 16;
    const __half* Brow = g_Bt + ((size_t)e * DMODEL + n0 + lr) * DMODEL + lh * 16;
    const uint32_t sAa = smem_u32(sA) + (uint32_t)(lr * 80 + lh * 32);
    const uint32_t sBa = smem_u32(sB) + (uint32_t)(lr * 80 + lh * 32);

    auto load_stage = [&](int t) {
        int buf = t % STAGES;
        int kc = t * BKc;
        uint32_t da = sAa + buf * STAGE_BYTES;
        uint32_t db = sBa + buf * STAGE_BYTES;
        cp16(da,      Arow + kc);
        cp16(da + 16, Arow + kc + 8);
        cp16(db,      Brow + kc);
        cp16(db + 16, Brow + kc + 8);
        CP_COMMIT();
    };

    float acc[2][8][4];
#pragma unroll
    for (int i = 0; i < 2; i++)
#pragma unroll
        for (int j = 0; j < 8; j++)
#pragma unroll
            for (int q = 0; q < 4; q++) acc[i][j][q] = 0.0f;

    // ldmatrix lane addressing (byte offsets within a stage)
    const int aRow = wm * 32 + (lane & 7) + ((lane >> 3) & 1) * 8;
    const int aK   = ((lane >> 4) & 1) * 8;
    const int bRow = wn * 64 + (lane & 7) + ((lane >> 4) & 1) * 8;
    const int bK   = ((lane >> 3) & 1) * 8;
    const uint32_t aLd = smem_u32(sA) + (uint32_t)(aRow * 80 + aK * 2);
    const uint32_t bLd = smem_u32(sB) + (uint32_t)(bRow * 80 + bK * 2);

    load_stage(0);
    load_stage(1);

    for (int t = 0; t < NCHUNK; t++) {
        const int buf = t % STAGES;
        // Drain rule: last iteration's group is the newest -> wait_group 0.
        if (t < NCHUNK - 1) { CP_WAIT1(); } else { CP_WAIT0(); }
        __syncthreads();
        if (t + 2 < NCHUNK) load_stage(t + 2);

        const uint32_t aBase = aLd + buf * STAGE_BYTES;
        const uint32_t bBase = bLd + buf * STAGE_BYTES;
#pragma unroll
        for (int k16 = 0; k16 < 2; k16++) {
            uint32_t a[2][4];
#pragma unroll
            for (int mt = 0; mt < 2; mt++)
                ldsm_x4(a[mt], aBase + mt * 16 * 80 + k16 * 32);
            uint32_t b[4][4];
#pragma unroll
            for (int nt2 = 0; nt2 < 4; nt2++)
                ldsm_x4(b[nt2], bBase + nt2 * 16 * 80 + k16 * 32);
#pragma unroll
            for (int mt = 0; mt < 2; mt++)
#pragma unroll
                for (int nt2 = 0; nt2 < 4; nt2++) {
                    mma16816(acc[mt][2 * nt2 + 0], a[mt], b[nt2][0], b[nt2][1]);
                    mma16816(acc[mt][2 * nt2 + 1], a[mt], b[nt2][2], b[nt2][3]);
                }
        }
    }

    // ---- epilogue: (acc + bias) -> g_y as fp16 ----
    const int qrow = lane >> 2;
    const int qcol = 2 * (lane & 3);
    const float* bcol = bias + (size_t)e * DMODEL + n0 + wn * 64 + qcol;
    float2 bv[8];
#pragma unroll
    for (int nt = 0; nt < 8; nt++) bv[nt] = *(const float2*)(bcol + nt * 8);

#pragma unroll
    for (int mt = 0; mt < 2; mt++) {
        int rbase = m0 + wm * 32 + mt * 16 + qrow;
#pragma unroll
        for (int half = 0; half < 2; half++) {
            int grow = rbase + half * 8;
            if (grow < r1) {
                __half* yr = g_y + (size_t)grow * DMODEL + n0 + wn * 64 + qcol;
#pragma unroll
                for (int nt = 0; nt < 8; nt++) {
                    __half2 hv = __floats2half2_rn(
                        acc[mt][nt][2 * half] + bv[nt].x,
                        acc[mt][nt][2 * half + 1] + bv[nt].y);
                    *(__half2*)(yr + nt * 8) = hv;
                }
            }
        }
    }
}

// ---------------- combine: out[n] = p0*y0 + p1*y1 (bias already in y) --------
__global__ void combine_kernel(const float* __restrict__ prob,
                               float* __restrict__ out) {
    int i = blockIdx.x * blockDim.x + threadIdx.x;   // over NTOK * 64 (8 cols)
    if (i >= NTOK * (DMODEL / 8)) return;
    int n  = i >> 6;
    int c8 = i & 63;
    float p0 = prob[2 * n], p1 = prob[2 * n + 1];
    int rr0 = g_row[2 * n], rr1 = g_row[2 * n + 1];

    uint4 u0 = ((const uint4*)g_y)[(size_t)rr0 * (DMODEL / 8) + c8];
    uint4 u1 = ((const uint4*)g_y)[(size_t)rr1 * (DMODEL / 8) + c8];
    const __half2* h0 = (const __half2*)&u0;
    const __half2* h1 = (const __half2*)&u1;

    float4* op = (float4*)out + (size_t)n * (DMODEL / 4) + 2 * c8;
#pragma unroll
    for (int q = 0; q < 2; q++) {
        float2 a0 = __half22float2(h0[2 * q + 0]);
        float2 a1 = __half22float2(h0[2 * q + 1]);
        float2 c0 = __half22float2(h1[2 * q + 0]);
        float2 c1 = __half22float2(h1[2 * q + 1]);
        float4 o;
        o.x = p0 * a0.x + p1 * c0.x;
        o.y = p0 * a0.y + p1 * c0.y;
        o.z = p0 * a1.x + p1 * c1.x;
        o.w = p0 * a1.y + p1 * c1.y;
        op[q] = o;
    }
}

// ---------------- launch -----------------------------------------------------
extern "C" void kernel_launch(void* const* d_in, const int* in_sizes, int n_in,
                              void* d_out, int out_size) {
    const float* x    = (const float*)d_in[0];
    const float* prob = (const float*)d_in[1];
    const int*   idx  = (const int*)d_in[2];
    const float* W    = (const float*)d_in[3];
    const float* bias = (const float*)d_in[4];

    static int smem_set = 0;
    const int SMEMB = STAGES * (BM * ASTR + BN * ASTR) * 2;  // 61440
    if (!smem_set) {
        cudaFuncSetAttribute(moe_gemm_kernel,
                             cudaFuncAttributeMaxDynamicSharedMemorySize, SMEMB);
        smem_set = 1;
    }

    // combine writes all NTOK*DMODEL output elems; zero only the tail (loss).
    if (out_size > NTOK * DMODEL) {
        cudaMemsetAsync((float*)d_out + NTOK * DMODEL, 0,
                        (size_t)(out_size - NTOK * DMODEL) * sizeof(float), 0);
    }

    k1_count_convx<<<NBLK_ROUTE + NBLK_CONVX, 256>>>(idx, x);
    k2_place_convw<<<NBLK_ROUTE + NBLK_CONVW, 256>>>(idx, W);

    dim3 ggrid(DMODEL / BN, NKROWS / BM, NEXP);   // (4, 256, 8); most exit early
    moe_gemm_kernel<<<ggrid, 256, SMEMB>>>(bias);

    int cthreads = NTOK * (DMODEL / 8);
    combine_kernel<<<(cthreads + 255) / 256, 256>>>(prob, (float*)d_out);
}

// round 9
// speedup vs baseline: 4.5918x; 1.0653x over previous
#include <cuda_runtime.h>
#include <cuda_fp16.h>
#include <cstdint>

// ---------------- problem constants ----------------------------------------
#define DMODEL 512
#define NEXP   8
#define NTOK   16384
#define NKROWS 32768          // NTOK * top_k
#define BM     128
#define BN     256            // CTA N tile (512 threads)
#define BKc    32             // fp16 k per chunk
#define NCHUNK (DMODEL / BKc) // 16
#define ASTR   40             // smem row stride in fp16 elems (32 + 8 pad = 80B)
#define STAGES 3
#define A_STAGE_BYTES (BM * ASTR * 2)   // 10240
#define B_STAGE_BYTES (BN * ASTR * 2)   // 20480

#define NBLK_ROUTE (NKROWS / 256)                     // 128
#define NBLK_CONVX (NTOK * DMODEL / 8 / 256)          // 4096
#define NBLK_CONVW (NEXP * (DMODEL / 32) * (DMODEL / 32))  // 2048

// ---------------- static device scratch -------------------------------------
__device__ int g_blkcnt[NBLK_ROUTE * NEXP];
__device__ int g_off[NEXP + 1];
__device__ int g_tok[NKROWS];
__device__ int g_row[NKROWS];
__device__ __half g_xf[NTOK * DMODEL];
__device__ __half g_Bt[NEXP * DMODEL * DMODEL];
__device__ __half g_y[(size_t)NKROWS * DMODEL];    // expert outputs + bias

// ---------------- helpers ----------------------------------------------------
__device__ __forceinline__ uint32_t smem_u32(const void* p) {
    uint32_t a;
    asm("{ .reg .u64 t; cvta.to.shared.u64 t, %1; cvt.u32.u64 %0, t; }"
        : "=r"(a) : "l"(p));
    return a;
}
__device__ __forceinline__ void cp16(uint32_t dst, const void* src) {
    asm volatile("cp.async.ca.shared.global [%0], [%1], 16;"
                 :: "r"(dst), "l"(src) : "memory");
}
#define CP_COMMIT() asm volatile("cp.async.commit_group;" ::: "memory")
#define CP_WAIT1()  asm volatile("cp.async.wait_group 1;" ::: "memory")
#define CP_WAIT0()  asm volatile("cp.async.wait_group 0;" ::: "memory")

__device__ __forceinline__ void ldsm_x4(uint32_t* r, uint32_t addr) {
    asm volatile("ldmatrix.sync.aligned.m8n8.x4.shared.b16 {%0,%1,%2,%3}, [%4];"
                 : "=r"(r[0]), "=r"(r[1]), "=r"(r[2]), "=r"(r[3]) : "r"(addr));
}
__device__ __forceinline__ void mma16816(float* c, const uint32_t* a,
                                         uint32_t b0, uint32_t b1) {
    asm volatile(
        "mma.sync.aligned.m16n8k16.row.col.f32.f16.f16.f32 "
        "{%0,%1,%2,%3}, {%4,%5,%6,%7}, {%8,%9}, {%0,%1,%2,%3};"
        : "+f"(c[0]), "+f"(c[1]), "+f"(c[2]), "+f"(c[3])
        : "r"(a[0]), "r"(a[1]), "r"(a[2]), "r"(a[3]), "r"(b0), "r"(b1));
}

// ---------------- K1: per-block histograms + x fp16 convert ------------------
__global__ void k1_count_convx(const int* __restrict__ idx,
                               const float* __restrict__ x) {
    const int b = blockIdx.x;
    const int t = threadIdx.x;
    if (b < NBLK_ROUTE) {
        __shared__ int sc[NEXP];
        if (t < NEXP) sc[t] = 0;
        __syncthreads();
        atomicAdd(&sc[idx[b * 256 + t]], 1);
        __syncthreads();
        if (t < NEXP) g_blkcnt[b * NEXP + t] = sc[t];
    } else {
        int i = (b - NBLK_ROUTE) * 256 + t;          // per 8 floats
        float4 v0 = ((const float4*)x)[2 * i];
        float4 v1 = ((const float4*)x)[2 * i + 1];
        __half2* dst = (__half2*)(g_xf + 8 * (size_t)i);
        dst[0] = __floats2half2_rn(v0.x, v0.y);
        dst[1] = __floats2half2_rn(v0.z, v0.w);
        dst[2] = __floats2half2_rn(v1.x, v1.y);
        dst[3] = __floats2half2_rn(v1.z, v1.w);
    }
}

// ---------------- K2: place tokens + W transpose/convert ---------------------
__global__ void k2_place_convw(const int* __restrict__ idx,
                               const float* __restrict__ W) {
    const int b = blockIdx.x;
    const int t = threadIdx.x;
    if (b < NBLK_ROUTE) {
        __shared__ int cnt[NBLK_ROUTE * NEXP];   // 4 KB
        __shared__ int stot[NEXP], sbase[NEXP], soff[NEXP + 1], scur[NEXP];
        for (int j = t; j < NBLK_ROUTE * NEXP; j += 256) cnt[j] = g_blkcnt[j];
        if (t < NEXP) scur[t] = 0;
        __syncthreads();
        if (t < NEXP) {
            int tot = 0, bb = 0;
            for (int blk = 0; blk < NBLK_ROUTE; blk++) {
                int c = cnt[blk * NEXP + t];
                if (blk < b) bb += c;
                tot += c;
            }
            stot[t] = tot;
            sbase[t] = bb;
        }
        __syncthreads();
        if (t == 0) {
            int acc = 0;
            for (int e2 = 0; e2 < NEXP; e2++) { soff[e2] = acc; acc += stot[e2]; }
            soff[NEXP] = acc;
        }
        __syncthreads();
        int i = b * 256 + t;
        int e = idx[i];
        int lp = atomicAdd(&scur[e], 1);
        int pos = soff[e] + sbase[e] + lp;
        g_tok[pos] = i >> 1;
        g_row[i] = pos;
        if (b == 0 && t <= NEXP) g_off[t] = soff[t];
    } else {
        __shared__ float tile[32][33];
        int w = b - NBLK_ROUTE;
        int e = w >> 8;
        int k0 = (w & 15) * 32;
        int n0 = ((w >> 4) & 15) * 32;
        int tx = t & 31, ty = t >> 5;
        const float* Wb = W + (size_t)e * DMODEL * DMODEL;
        for (int r = ty; r < 32; r += 8)
            tile[r][tx] = Wb[(size_t)(k0 + r) * DMODEL + n0 + tx];
        __syncthreads();
        __half* Be = g_Bt + (size_t)e * DMODEL * DMODEL;
        for (int r = ty; r < 32; r += 8)
            Be[(size_t)(n0 + r) * DMODEL + k0 + tx] = __float2half_rn(tile[tx][r]);
    }
}

// ---------------- grouped GEMM: 128x256 CTA, 512 threads ---------------------
__global__ __launch_bounds__(512, 1)
void moe_gemm_kernel(const float* __restrict__ bias) {
    const int e = blockIdx.z;
    const int r0 = g_off[e], r1 = g_off[e + 1];
    const int m0 = r0 + blockIdx.y * BM;
    if (m0 >= r1) return;
    const int n0 = blockIdx.x * BN;

    extern __shared__ __half dsm[];
    __half* sA = dsm;                                   // [STAGES][BM*ASTR]
    __half* sB = dsm + STAGES * BM * ASTR;              // [STAGES][BN*ASTR]
    __shared__ int sTok[BM];

    const int tid  = threadIdx.x;
    const int wid  = tid >> 5;
    const int lane = tid & 31;
    const int wm   = wid & 3;     // 4 M slices of 32 rows
    const int wn   = wid >> 2;    // 4 N slices of 64 cols

    if (tid < BM) {
        int r = m0 + tid;
        sTok[tid] = (r < r1) ? g_tok[r] : g_tok[m0];
    }
    __syncthreads();

    // global-load mapping:
    // A: 128 rows x 64B / 512 thr -> each thread 16B of one row
    const int lrA = tid >> 2, lqA = tid & 3;
    // B: 256 rows x 64B -> 1024 16B-chunks -> 2 per thread
    const int c0 = tid, c1 = tid + 512;
    const int lrB0 = c0 >> 2, lqB0 = c0 & 3;
    const int lrB1 = c1 >> 2, lqB1 = c1 & 3;

    const __half* Arow  = g_xf + (size_t)sTok[lrA] * DMODEL + lqA * 8;
    const __half* Brow0 = g_Bt + ((size_t)e * DMODEL + n0 + lrB0) * DMODEL + lqB0 * 8;
    const __half* Brow1 = g_Bt + ((size_t)e * DMODEL + n0 + lrB1) * DMODEL + lqB1 * 8;
    const uint32_t sAa  = smem_u32(sA) + (uint32_t)(lrA * 80 + lqA * 16);
    const uint32_t sBa0 = smem_u32(sB) + (uint32_t)(lrB0 * 80 + lqB0 * 16);
    const uint32_t sBa1 = smem_u32(sB) + (uint32_t)(lrB1 * 80 + lqB1 * 16);

    auto load_stage = [&](int t) {
        int buf = t % STAGES;
        int kc = t * BKc;
        cp16(sAa  + buf * A_STAGE_BYTES, Arow  + kc);
        cp16(sBa0 + buf * B_STAGE_BYTES, Brow0 + kc);
        cp16(sBa1 + buf * B_STAGE_BYTES, Brow1 + kc);
        CP_COMMIT();
    };

    float acc[2][8][4];
#pragma unroll
    for (int i = 0; i < 2; i++)
#pragma unroll
        for (int j = 0; j < 8; j++)
#pragma unroll
            for (int q = 0; q < 4; q++) acc[i][j][q] = 0.0f;

    // ldmatrix lane addressing
    const int aRow = wm * 32 + (lane & 7) + ((lane >> 3) & 1) * 8;
    const int aK   = ((lane >> 4) & 1) * 8;
    const int bRow = wn * 64 + (lane & 7) + ((lane >> 4) & 1) * 8;
    const int bK   = ((lane >> 3) & 1) * 8;
    const uint32_t aLd = smem_u32(sA) + (uint32_t)(aRow * 80 + aK * 2);
    const uint32_t bLd = smem_u32(sB) + (uint32_t)(bRow * 80 + bK * 2);

    load_stage(0);
    load_stage(1);

    for (int t = 0; t < NCHUNK; t++) {
        const int buf = t % STAGES;
        if (t < NCHUNK - 1) { CP_WAIT1(); } else { CP_WAIT0(); }
        __syncthreads();
        if (t + 2 < NCHUNK) load_stage(t + 2);

        const uint32_t aBase = aLd + buf * A_STAGE_BYTES;
        const uint32_t bBase = bLd + buf * B_STAGE_BYTES;
#pragma unroll
        for (int k16 = 0; k16 < 2; k16++) {
            uint32_t a[2][4];
#pragma unroll
            for (int mt = 0; mt < 2; mt++)
                ldsm_x4(a[mt], aBase + mt * 16 * 80 + k16 * 32);
            uint32_t b[4][4];
#pragma unroll
            for (int nt2 = 0; nt2 < 4; nt2++)
                ldsm_x4(b[nt2], bBase + nt2 * 16 * 80 + k16 * 32);
#pragma unroll
            for (int mt = 0; mt < 2; mt++)
#pragma unroll
                for (int nt2 = 0; nt2 < 4; nt2++) {
                    mma16816(acc[mt][2 * nt2 + 0], a[mt], b[nt2][0], b[nt2][1]);
                    mma16816(acc[mt][2 * nt2 + 1], a[mt], b[nt2][2], b[nt2][3]);
                }
        }
    }

    // ---- epilogue: (acc + bias) -> g_y as fp16 ----
    const int qrow = lane >> 2;
    const int qcol = 2 * (lane & 3);
    const float* bcol = bias + (size_t)e * DMODEL + n0 + wn * 64 + qcol;
    float2 bv[8];
#pragma unroll
    for (int nt = 0; nt < 8; nt++) bv[nt] = *(const float2*)(bcol + nt * 8);

#pragma unroll
    for (int mt = 0; mt < 2; mt++) {
        int rbase = m0 + wm * 32 + mt * 16 + qrow;
#pragma unroll
        for (int half = 0; half < 2; half++) {
            int grow = rbase + half * 8;
            if (grow < r1) {
                __half* yr = g_y + (size_t)grow * DMODEL + n0 + wn * 64 + qcol;
#pragma unroll
                for (int nt = 0; nt < 8; nt++) {
                    __half2 hv = __floats2half2_rn(
                        acc[mt][nt][2 * half] + bv[nt].x,
                        acc[mt][nt][2 * half + 1] + bv[nt].y);
                    *(__half2*)(yr + nt * 8) = hv;
                }
            }
        }
    }
}

// ---------------- combine: out[n] = p0*y0 + p1*y1; extra blocks zero tail ----
#define COMBINE_MAIN_BLOCKS (NTOK * (DMODEL / 16) / 256)   // 2048
__global__ void combine_kernel(const float* __restrict__ prob,
                               float* __restrict__ out, int tail_elems) {
    int b = blockIdx.x;
    if (b >= COMBINE_MAIN_BLOCKS) {
        int j = (b - COMBINE_MAIN_BLOCKS) * 256 + threadIdx.x;
        if (j < tail_elems) out[NTOK * DMODEL + j] = 0.0f;
        return;
    }
    int i = b * 256 + threadIdx.x;     // over NTOK * 32 groups of 16 cols
    int n   = i >> 5;
    int c16 = i & 31;
    float p0 = prob[2 * n], p1 = prob[2 * n + 1];
    int rr0 = g_row[2 * n], rr1 = g_row[2 * n + 1];

    const uint4* y0p = (const uint4*)g_y + (size_t)rr0 * (DMODEL / 8) + 2 * c16;
    const uint4* y1p = (const uint4*)g_y + (size_t)rr1 * (DMODEL / 8) + 2 * c16;
    uint4 u0a = y0p[0], u0b = y0p[1];
    uint4 u1a = y1p[0], u1b = y1p[1];

    float4* op = (float4*)out + (size_t)n * (DMODEL / 4) + 4 * c16;
    const __half2* h0a = (const __half2*)&u0a;
    const __half2* h0b = (const __half2*)&u0b;
    const __half2* h1a = (const __half2*)&u1a;
    const __half2* h1b = (const __half2*)&u1b;
#pragma unroll
    for (int q = 0; q < 4; q++) {
        const __half2* ha = (q < 2) ? h0a : h0b;
        const __half2* hb = (q < 2) ? h1a : h1b;
        int qq = q & 1;
        float2 a0 = __half22float2(ha[2 * qq + 0]);
        float2 a1 = __half22float2(ha[2 * qq + 1]);
        float2 c0 = __half22float2(hb[2 * qq + 0]);
        float2 c1 = __half22float2(hb[2 * qq + 1]);
        float4 o;
        o.x = p0 * a0.x + p1 * c0.x;
        o.y = p0 * a0.y + p1 * c0.y;
        o.z = p0 * a1.x + p1 * c1.x;
        o.w = p0 * a1.y + p1 * c1.y;
        op[q] = o;
    }
}

// ---------------- launch -----------------------------------------------------
extern "C" void kernel_launch(void* const* d_in, const int* in_sizes, int n_in,
                              void* d_out, int out_size) {
    const float* x    = (const float*)d_in[0];
    const float* prob = (const float*)d_in[1];
    const int*   idx  = (const int*)d_in[2];
    const float* W    = (const float*)d_in[3];
    const float* bias = (const float*)d_in[4];

    static int smem_set = 0;
    const int SMEMB = STAGES * (A_STAGE_BYTES + B_STAGE_BYTES);  // 92160
    if (!smem_set) {
        cudaFuncSetAttribute(moe_gemm_kernel,
                             cudaFuncAttributeMaxDynamicSharedMemorySize, SMEMB);
        smem_set = 1;
    }

    k1_count_convx<<<NBLK_ROUTE + NBLK_CONVX, 256>>>(idx, x);
    k2_place_convw<<<NBLK_ROUTE + NBLK_CONVW, 256>>>(idx, W);

    dim3 ggrid(DMODEL / BN, NKROWS / BM, NEXP);   // (2, 256, 8)
    moe_gemm_kernel<<<ggrid, 512, SMEMB>>>(bias);

    int tail = out_size - NTOK * DMODEL;
    if (tail < 0) tail = 0;
    int tail_blocks = (tail + 255) / 256;
    combine_kernel<<<COMBINE_MAIN_BLOCKS + tail_blocks, 256>>>(
        prob, (float*)d_out, tail);
}